// round 1
// baseline (speedup 1.0000x reference)
#include <cuda_runtime.h>
#include <math.h>

#define NN   100000
#define EE   1600000
#define ENC  128
#define PI_  98
#define KIN  226          // ENC + PI
#define KC   232          // KIN padded to multiple of 8
#define MH   512          // 4 stacked [*,128] outputs
#define EMB  128

// ---------------- scratch (static device globals; no allocation) ----------------
__device__ float g_xc  [(size_t)NN * KC];    // concat(x, d2an) zero-padded
__device__ float g_h   [(size_t)NN * MH];    // stacked h1/h2 for both sublayers
__device__ float g_out0[(size_t)NN * EMB];
__device__ float g_out1[(size_t)NN * EMB];
__device__ float g_xm  [(size_t)NN * EMB];
__device__ float g_dis0[NN];
__device__ float g_dis1[NN];
__device__ float g_Wc  [MH * KC];            // stage-1 fused weights
__device__ float g_Wc2 [MH * ENC];           // stage-2 stacked weights

// ---------------- degree / normalization ----------------
__global__ void k_deg_init() {
    int i = blockIdx.x * blockDim.x + threadIdx.x;
    if (i < NN) { g_dis0[i] = 1.0f; g_dis1[i] = 1.0f; }   // self-loop counts
}

__global__ void k_deg_count(const int* __restrict__ ei0, const int* __restrict__ ei1) {
    int e = blockIdx.x * blockDim.x + threadIdx.x;
    if (e < EE) {
        atomicAdd(&g_dis0[ei0[EE + e]], 1.0f);
        atomicAdd(&g_dis1[ei1[EE + e]], 1.0f);
    }
}

__global__ void k_dis() {
    int i = blockIdx.x * blockDim.x + threadIdx.x;
    if (i < NN) { g_dis0[i] = rsqrtf(g_dis0[i]); g_dis1[i] = rsqrtf(g_dis1[i]); }
}

// ---------------- build concat input (zero-padded to KC) ----------------
__global__ void k_build_xc(const float* __restrict__ x, const float* __restrict__ d2) {
    int i = blockIdx.x * blockDim.x + threadIdx.x;
    if (i >= NN * KC) return;
    int n = i / KC, k = i - n * KC;
    float v = 0.0f;
    if (k < ENC)       v = x[n * ENC + k];
    else if (k < KIN)  v = d2[n * PI_ + (k - ENC)];
    g_xc[i] = v;
}

// ---------------- fused weights: Wc[m] = Wsel[m%128] @ nodeWsel ----------------
__global__ void k_build_Wc(const float* __restrict__ W1a, const float* __restrict__ W1b,
                           const float* __restrict__ W2a, const float* __restrict__ W2b,
                           const float* __restrict__ nW1, const float* __restrict__ nW2) {
    int i = blockIdx.x * blockDim.x + threadIdx.x;
    if (i >= MH * KC) return;
    int m = i / KC, k = i - m * KC;
    float v = 0.0f;
    if (k < KIN) {
        const float* Ws = (m < 128) ? W1a : (m < 256) ? W1b : (m < 384) ? W2a : W2b;
        const float* nW = (m < 256) ? nW1 : nW2;
        int mm = m & 127;
        float s = 0.0f;
#pragma unroll 8
        for (int j = 0; j < ENC; j++) s = fmaf(Ws[mm * ENC + j], nW[j * KIN + k], s);
        v = s;
    }
    g_Wc[i] = v;
}

__global__ void k_build_Wc2(const float* __restrict__ W3a, const float* __restrict__ W3b,
                            const float* __restrict__ W4a, const float* __restrict__ W4b) {
    int i = blockIdx.x * blockDim.x + threadIdx.x;
    if (i >= MH * ENC) return;
    int m = i / ENC, k = i - m * ENC;
    const float* Ws = (m < 128) ? W3a : (m < 256) ? W3b : (m < 384) ? W4a : W4b;
    g_Wc2[i] = Ws[(m & 127) * ENC + k];
}

// ---------------- GEMM: C[N,512] = A[N,K] * W[512,K]^T ----------------
__global__ __launch_bounds__(256, 2)
void k_gemm(int stage) {
    const float* __restrict__ A = stage ? g_xm  : g_xc;
    const float* __restrict__ W = stage ? g_Wc2 : g_Wc;
    const int K = stage ? ENC : KC;

    __shared__ float As[2][8][128];
    __shared__ float Ws[2][8][128];

    const int tid = threadIdx.x;
    const int bn  = blockIdx.x * 128;   // node base
    const int bm  = blockIdx.y * 128;   // out-col base
    const int lr  = tid >> 1;           // tile row 0..127
    const int lk  = (tid & 1) * 4;      // k sub-offset 0/4
    const int tx  = tid & 15;
    const int ty  = tid >> 4;

    const int  arow = bn + lr;
    const bool aval = (arow < NN);
    const float* Abase = A + (size_t)arow * K + lk;
    const float* Wbase = W + (size_t)(bm + lr) * K + lk;

    float acc[8][8];
#pragma unroll
    for (int i = 0; i < 8; i++)
#pragma unroll
        for (int j = 0; j < 8; j++) acc[i][j] = 0.0f;

    const int nk = K >> 3;

    auto load_tile = [&](int kt, int buf) {
        float4 a = make_float4(0.f, 0.f, 0.f, 0.f);
        if (aval) a = *(const float4*)(Abase + kt * 8);
        As[buf][lk + 0][lr] = a.x;
        As[buf][lk + 1][lr] = a.y;
        As[buf][lk + 2][lr] = a.z;
        As[buf][lk + 3][lr] = a.w;
        float4 w = *(const float4*)(Wbase + kt * 8);
        Ws[buf][lk + 0][lr] = w.x;
        Ws[buf][lk + 1][lr] = w.y;
        Ws[buf][lk + 2][lr] = w.z;
        Ws[buf][lk + 3][lr] = w.w;
    };

    load_tile(0, 0);
    __syncthreads();

    for (int kt = 0; kt < nk; kt++) {
        int buf = kt & 1;
        if (kt + 1 < nk) load_tile(kt + 1, buf ^ 1);
#pragma unroll
        for (int k = 0; k < 8; k++) {
            float4 a0 = *(const float4*)&As[buf][k][ty * 4];
            float4 a1 = *(const float4*)&As[buf][k][64 + ty * 4];
            float4 b0 = *(const float4*)&Ws[buf][k][tx * 4];
            float4 b1 = *(const float4*)&Ws[buf][k][64 + tx * 4];
            float a[8] = {a0.x, a0.y, a0.z, a0.w, a1.x, a1.y, a1.z, a1.w};
            float b[8] = {b0.x, b0.y, b0.z, b0.w, b1.x, b1.y, b1.z, b1.w};
#pragma unroll
            for (int i = 0; i < 8; i++)
#pragma unroll
                for (int j = 0; j < 8; j++) acc[i][j] = fmaf(a[i], b[j], acc[i][j]);
        }
        __syncthreads();
    }

#pragma unroll
    for (int h = 0; h < 2; h++) {
#pragma unroll
        for (int ii = 0; ii < 4; ii++) {
            int row = bn + h * 64 + ty * 4 + ii;
            if (row < NN) {
                float* Cr = g_h + (size_t)row * MH + bm;
#pragma unroll
                for (int g = 0; g < 2; g++) {
                    float4 v = make_float4(acc[h * 4 + ii][g * 4 + 0],
                                           acc[h * 4 + ii][g * 4 + 1],
                                           acc[h * 4 + ii][g * 4 + 2],
                                           acc[h * 4 + ii][g * 4 + 3]);
                    *(float4*)(Cr + g * 64 + tx * 4) = v;
                }
            }
        }
    }
}

// ---------------- self-loop init: out = dis^2*h1 + h2 (einv(1)=1) ----------------
__global__ void k_selfinit() {
    int i = blockIdx.x * blockDim.x + threadIdx.x;
    if (i >= NN * 32) return;
    int n = i >> 5, q = (i & 31) * 4;
    float s0 = g_dis0[n]; s0 *= s0;
    float s1 = g_dis1[n]; s1 *= s1;
    const float* hr = g_h + (size_t)n * MH;
    float4 a = *(const float4*)(hr + q);
    float4 b = *(const float4*)(hr + 128 + q);
    float4 c = *(const float4*)(hr + 256 + q);
    float4 d = *(const float4*)(hr + 384 + q);
    float4 o0 = make_float4(fmaf(s0, a.x, b.x), fmaf(s0, a.y, b.y),
                            fmaf(s0, a.z, b.z), fmaf(s0, a.w, b.w));
    float4 o1 = make_float4(fmaf(s1, c.x, d.x), fmaf(s1, c.y, d.y),
                            fmaf(s1, c.z, d.z), fmaf(s1, c.w, d.w));
    *(float4*)(g_out0 + (size_t)n * EMB + q) = o0;
    *(float4*)(g_out1 + (size_t)n * EMB + q) = o1;
}

// ---------------- edge scatter: one warp per edge, vector red ----------------
__global__ __launch_bounds__(256)
void k_scatter(const int* __restrict__ ei, const float* __restrict__ ew, int which) {
    int gid = blockIdx.x * blockDim.x + threadIdx.x;
    int e = gid >> 5;
    if (e >= EE) return;
    int lane = gid & 31;
    const float* dis = which ? g_dis1 : g_dis0;
    float* out = which ? g_out1 : g_out0;
    const int off = which * 256;

    int   r = __ldg(&ei[e]);
    int   c = __ldg(&ei[EE + e]);
    float w = __ldg(&ew[e]);
    float einv = (w > 0.0f) ? fminf(rsqrtf(w), 1.0f) : 0.0f;
    float dn   = dis[r] * dis[c];

    const float* hr = g_h + (size_t)r * MH + off + lane * 4;
    float4 a = *(const float4*)hr;
    float4 b = *(const float4*)(hr + 128);
    float4 v = make_float4(fmaf(dn, a.x, einv * b.x), fmaf(dn, a.y, einv * b.y),
                           fmaf(dn, a.z, einv * b.z), fmaf(dn, a.w, einv * b.w));
    float* p = out + (size_t)c * EMB + lane * 4;
    asm volatile("red.global.add.v4.f32 [%0], {%1,%2,%3,%4};"
                 :: "l"(p), "f"(v.x), "f"(v.y), "f"(v.z), "f"(v.w) : "memory");
}

// ---------------- combine: 0.5*relu(out0) + 0.5*relu(out1) ----------------
__global__ void k_combine(float* __restrict__ dst_ext, int use_ext) {
    int i = blockIdx.x * blockDim.x + threadIdx.x;
    if (i >= NN * 32) return;
    float* dst = use_ext ? dst_ext : g_xm;
    float4 a = ((const float4*)g_out0)[i];
    float4 b = ((const float4*)g_out1)[i];
    float4 r = make_float4(0.5f * (fmaxf(a.x, 0.f) + fmaxf(b.x, 0.f)),
                           0.5f * (fmaxf(a.y, 0.f) + fmaxf(b.y, 0.f)),
                           0.5f * (fmaxf(a.z, 0.f) + fmaxf(b.z, 0.f)),
                           0.5f * (fmaxf(a.w, 0.f) + fmaxf(b.w, 0.f)));
    ((float4*)dst)[i] = r;
}

// ---------------- launch ----------------
extern "C" void kernel_launch(void* const* d_in, const int* in_sizes, int n_in,
                              void* d_out, int out_size) {
    const float* x    = (const float*)d_in[0];
    const float* d2an = (const float*)d_in[1];
    const int*   ei0  = (const int*)  d_in[2];
    const float* ew0  = (const float*)d_in[3];
    const int*   ei1  = (const int*)  d_in[4];
    const float* ew1  = (const float*)d_in[5];
    const float* nW1  = (const float*)d_in[6];
    const float* nW2  = (const float*)d_in[7];
    const float* W1a  = (const float*)d_in[8];
    const float* W1b  = (const float*)d_in[9];
    const float* W2a  = (const float*)d_in[10];
    const float* W2b  = (const float*)d_in[11];
    const float* W3a  = (const float*)d_in[12];
    const float* W3b  = (const float*)d_in[13];
    const float* W4a  = (const float*)d_in[14];
    const float* W4b  = (const float*)d_in[15];
    float* out = (float*)d_out;

    const int TB = 256;
    k_deg_init <<<(NN + TB - 1) / TB, TB>>>();
    k_deg_count<<<(EE + TB - 1) / TB, TB>>>(ei0, ei1);
    k_dis      <<<(NN + TB - 1) / TB, TB>>>();

    k_build_xc <<<(NN * KC + TB - 1) / TB, TB>>>(x, d2an);
    k_build_Wc <<<(MH * KC + TB - 1) / TB, TB>>>(W1a, W1b, W2a, W2b, nW1, nW2);

    dim3 gg((NN + 127) / 128, MH / 128);
    const int sg = (EE * 32 + TB - 1) / TB;
    const int cg = (NN * 32 + TB - 1) / TB;

    // ---- stage 1 ----
    k_gemm    <<<gg, 256>>>(0);
    k_selfinit<<<cg, TB>>>();
    k_scatter <<<sg, TB>>>(ei0, ew0, 0);
    k_scatter <<<sg, TB>>>(ei1, ew1, 1);
    k_combine <<<cg, TB>>>(nullptr, 0);          // -> g_xm

    // ---- stage 2 ----
    k_build_Wc2<<<(MH * ENC + TB - 1) / TB, TB>>>(W3a, W3b, W4a, W4b);
    k_gemm    <<<gg, 256>>>(1);
    k_selfinit<<<cg, TB>>>();
    k_scatter <<<sg, TB>>>(ei0, ew0, 0);
    k_scatter <<<sg, TB>>>(ei1, ew1, 1);
    k_combine <<<cg, TB>>>(out, 1);              // -> d_out
}

// round 2
// speedup vs baseline: 1.2035x; 1.2035x over previous
#include <cuda_runtime.h>
#include <cuda_fp16.h>
#include <math.h>

#define NN   100000
#define EE   1600000
#define ENC  128
#define PI_  98
#define KIN  226          // ENC + PI
#define KC   232          // KIN padded to multiple of 8
#define MH   512          // 4 stacked [*,128] outputs
#define EMB  128

typedef unsigned long long ull;

// ---------------- scratch (static device globals; no allocation) ----------------
__device__ float   g_xc  [(size_t)NN * KC];     // concat(x, d2an) zero-padded
__device__ __half2 g_hh  [(size_t)NN * (MH/2)]; // stacked h1/h2 (fp16)
__device__ float   g_out0[(size_t)NN * EMB];
__device__ float   g_out1[(size_t)NN * EMB];
__device__ float   g_xm  [(size_t)NN * EMB];
__device__ float   g_dis0[NN];
__device__ float   g_dis1[NN];
__device__ float   g_Wc  [MH * KC];             // stage-1 fused weights
__device__ float   g_Wc2 [MH * ENC];            // stage-2 stacked weights

// ---------------- f32x2 helpers ----------------
__device__ __forceinline__ void fma2(ull &d, ull a, ull b) {
    asm("fma.rn.f32x2 %0, %1, %2, %0;" : "+l"(d) : "l"(a), "l"(b));
}
__device__ __forceinline__ ull pack2(float v) {
    ull r; asm("mov.b64 %0, {%1, %1};" : "=l"(r) : "f"(v)); return r;
}
__device__ __forceinline__ float2 unpack2(ull v) {
    float2 r; asm("mov.b64 {%0, %1}, %2;" : "=f"(r.x), "=f"(r.y) : "l"(v)); return r;
}

// ---------------- degree / normalization ----------------
__global__ void k_deg_init() {
    int i = blockIdx.x * blockDim.x + threadIdx.x;
    if (i < NN) { g_dis0[i] = 1.0f; g_dis1[i] = 1.0f; }   // self-loop counts
}

__global__ void k_deg_count(const int* __restrict__ ei0, const int* __restrict__ ei1) {
    int e = blockIdx.x * blockDim.x + threadIdx.x;
    if (e < EE) {
        atomicAdd(&g_dis0[ei0[EE + e]], 1.0f);
        atomicAdd(&g_dis1[ei1[EE + e]], 1.0f);
    }
}

__global__ void k_dis() {
    int i = blockIdx.x * blockDim.x + threadIdx.x;
    if (i < NN) { g_dis0[i] = rsqrtf(g_dis0[i]); g_dis1[i] = rsqrtf(g_dis1[i]); }
}

// ---------------- build concat input (block per node, coalesced) ----------------
__global__ void k_build_xc(const float* __restrict__ x, const float* __restrict__ d2) {
    int n = blockIdx.x;
    int k = threadIdx.x;
    if (k >= KC) return;
    float v = 0.0f;
    if (k < ENC)       v = x[n * ENC + k];
    else if (k < KIN)  v = d2[n * PI_ + (k - ENC)];
    g_xc[(size_t)n * KC + k] = v;
}

// ---------------- fused weights: Wc[m] = Wsel[m%128] @ nodeWsel ----------------
__global__ void k_build_Wc(const float* __restrict__ W1a, const float* __restrict__ W1b,
                           const float* __restrict__ W2a, const float* __restrict__ W2b,
                           const float* __restrict__ nW1, const float* __restrict__ nW2) {
    int i = blockIdx.x * blockDim.x + threadIdx.x;
    if (i >= MH * KC) return;
    int m = i / KC, k = i - m * KC;
    float v = 0.0f;
    if (k < KIN) {
        const float* Ws = (m < 128) ? W1a : (m < 256) ? W1b : (m < 384) ? W2a : W2b;
        const float* nW = (m < 256) ? nW1 : nW2;
        int mm = m & 127;
        float s = 0.0f;
#pragma unroll 8
        for (int j = 0; j < ENC; j++) s = fmaf(Ws[mm * ENC + j], nW[j * KIN + k], s);
        v = s;
    }
    g_Wc[i] = v;
}

__global__ void k_build_Wc2(const float* __restrict__ W3a, const float* __restrict__ W3b,
                            const float* __restrict__ W4a, const float* __restrict__ W4b) {
    int i = blockIdx.x * blockDim.x + threadIdx.x;
    if (i >= MH * ENC) return;
    int m = i / ENC, k = i - m * ENC;
    const float* Ws = (m < 128) ? W3a : (m < 256) ? W3b : (m < 384) ? W4a : W4b;
    g_Wc2[i] = Ws[(m & 127) * ENC + k];
}

// ---------------- GEMM: C[N,512] = A[N,K] * W[512,K]^T, packed f32x2, fp16 out ----------------
__global__ __launch_bounds__(256, 2)
void k_gemm(int stage) {
    const float* __restrict__ A = stage ? g_xm  : g_xc;
    const float* __restrict__ W = stage ? g_Wc2 : g_Wc;
    const int K = stage ? ENC : KC;

    __shared__ float As[2][8][128];
    __shared__ float Bs[2][8][128];

    const int tid = threadIdx.x;
    const int bn  = blockIdx.x * 128;   // node base
    const int bm  = blockIdx.y * 128;   // out-col base
    const int lr  = tid >> 1;           // tile row 0..127
    const int lk  = (tid & 1) * 4;      // k sub-offset 0/4
    const int tx  = tid & 15;
    const int ty  = tid >> 4;

    const int  arow = bn + lr;
    const bool aval = (arow < NN);
    const float* Abase = A + (size_t)arow * K + lk;
    const float* Wbase = W + (size_t)(bm + lr) * K + lk;

    ull acc[8][4];   // 8 rows x 4 col-pairs (8 columns)
#pragma unroll
    for (int i = 0; i < 8; i++)
#pragma unroll
        for (int j = 0; j < 4; j++) acc[i][j] = 0ULL;

    const int nk = K >> 3;

    auto load_tile = [&](int kt, int buf) {
        float4 a = make_float4(0.f, 0.f, 0.f, 0.f);
        if (aval) a = *(const float4*)(Abase + kt * 8);
        As[buf][lk + 0][lr] = a.x;
        As[buf][lk + 1][lr] = a.y;
        As[buf][lk + 2][lr] = a.z;
        As[buf][lk + 3][lr] = a.w;
        float4 w = *(const float4*)(Wbase + kt * 8);
        Bs[buf][lk + 0][lr] = w.x;
        Bs[buf][lk + 1][lr] = w.y;
        Bs[buf][lk + 2][lr] = w.z;
        Bs[buf][lk + 3][lr] = w.w;
    };

    load_tile(0, 0);
    __syncthreads();

    for (int kt = 0; kt < nk; kt++) {
        int buf = kt & 1;
        if (kt + 1 < nk) load_tile(kt + 1, buf ^ 1);
#pragma unroll
        for (int k = 0; k < 8; k++) {
            float4 a0 = *(const float4*)&As[buf][k][ty * 4];
            float4 a1 = *(const float4*)&As[buf][k][64 + ty * 4];
            ulonglong2 b01 = *(const ulonglong2*)&Bs[buf][k][tx * 4];
            ulonglong2 b23 = *(const ulonglong2*)&Bs[buf][k][64 + tx * 4];
            float av[8] = {a0.x, a0.y, a0.z, a0.w, a1.x, a1.y, a1.z, a1.w};
#pragma unroll
            for (int i = 0; i < 8; i++) {
                ull ap = pack2(av[i]);
                fma2(acc[i][0], ap, b01.x);
                fma2(acc[i][1], ap, b01.y);
                fma2(acc[i][2], ap, b23.x);
                fma2(acc[i][3], ap, b23.y);
            }
        }
        __syncthreads();
    }

    // store as fp16 pairs
#pragma unroll
    for (int h = 0; h < 2; h++) {
#pragma unroll
        for (int ii = 0; ii < 4; ii++) {
            int row = bn + h * 64 + ty * 4 + ii;
            if (row < NN) {
                __half2* Cr = g_hh + (size_t)row * (MH / 2) + (bm >> 1);
#pragma unroll
                for (int g = 0; g < 2; g++) {
                    float2 p0 = unpack2(acc[h * 4 + ii][g * 2 + 0]);
                    float2 p1 = unpack2(acc[h * 4 + ii][g * 2 + 1]);
                    __half2 q0 = __floats2half2_rn(p0.x, p0.y);
                    __half2 q1 = __floats2half2_rn(p1.x, p1.y);
                    uint2 st;
                    st.x = *(unsigned*)&q0;
                    st.y = *(unsigned*)&q1;
                    *(uint2*)(Cr + (g * 64 + tx * 4) / 2) = st;
                }
            }
        }
    }
}

// ---------------- self-loop init: out = dis^2*h1 + h2 (einv(1)=1) ----------------
__global__ void k_selfinit() {
    int i = blockIdx.x * blockDim.x + threadIdx.x;
    if (i >= NN * 32) return;
    int n = i >> 5, c = (i & 31) * 2;   // half2 index within 64-half2 region
    float s0 = g_dis0[n]; s0 *= s0;
    float s1 = g_dis1[n]; s1 *= s1;
    const __half2* hr = g_hh + (size_t)n * (MH / 2);
    float2 a0 = __half22float2(hr[c]),        a1 = __half22float2(hr[c + 1]);
    float2 b0 = __half22float2(hr[64 + c]),   b1 = __half22float2(hr[64 + c + 1]);
    float2 c0 = __half22float2(hr[128 + c]),  c1 = __half22float2(hr[128 + c + 1]);
    float2 d0 = __half22float2(hr[192 + c]),  d1 = __half22float2(hr[192 + c + 1]);
    float4 o0 = make_float4(fmaf(s0, a0.x, b0.x), fmaf(s0, a0.y, b0.y),
                            fmaf(s0, a1.x, b1.x), fmaf(s0, a1.y, b1.y));
    float4 o1 = make_float4(fmaf(s1, c0.x, d0.x), fmaf(s1, c0.y, d0.y),
                            fmaf(s1, c1.x, d1.x), fmaf(s1, c1.y, d1.y));
    *(float4*)(g_out0 + (size_t)n * EMB + (i & 31) * 4) = o0;
    *(float4*)(g_out1 + (size_t)n * EMB + (i & 31) * 4) = o1;
}

// ---------------- edge scatter: one warp per edge, fp16 gather, fp32 vector red ----------------
__global__ __launch_bounds__(256)
void k_scatter(const int* __restrict__ ei, const float* __restrict__ ew, int which) {
    int gid = blockIdx.x * blockDim.x + threadIdx.x;
    int e = gid >> 5;
    if (e >= EE) return;
    int lane = gid & 31;
    const float* dis = which ? g_dis1 : g_dis0;
    float* out = which ? g_out1 : g_out0;

    int   r = __ldg(&ei[e]);
    int   c = __ldg(&ei[EE + e]);
    float w = __ldg(&ew[e]);
    float einv = (w > 0.0f) ? fminf(rsqrtf(w), 1.0f) : 0.0f;
    float dn   = dis[r] * dis[c];

    const __half2* hp = g_hh + (size_t)r * (MH / 2) + which * 128 + lane * 2;
    float2 fa0 = __half22float2(hp[0]);
    float2 fa1 = __half22float2(hp[1]);
    float2 fb0 = __half22float2(hp[64]);
    float2 fb1 = __half22float2(hp[65]);
    float4 v = make_float4(fmaf(dn, fa0.x, einv * fb0.x), fmaf(dn, fa0.y, einv * fb0.y),
                           fmaf(dn, fa1.x, einv * fb1.x), fmaf(dn, fa1.y, einv * fb1.y));
    float* p = out + (size_t)c * EMB + lane * 4;
    asm volatile("red.global.add.v4.f32 [%0], {%1,%2,%3,%4};"
                 :: "l"(p), "f"(v.x), "f"(v.y), "f"(v.z), "f"(v.w) : "memory");
}

// ---------------- combine: 0.5*relu(out0) + 0.5*relu(out1) ----------------
__global__ void k_combine(float* __restrict__ dst_ext, int use_ext) {
    int i = blockIdx.x * blockDim.x + threadIdx.x;
    if (i >= NN * 32) return;
    float* dst = use_ext ? dst_ext : g_xm;
    float4 a = ((const float4*)g_out0)[i];
    float4 b = ((const float4*)g_out1)[i];
    float4 r = make_float4(0.5f * (fmaxf(a.x, 0.f) + fmaxf(b.x, 0.f)),
                           0.5f * (fmaxf(a.y, 0.f) + fmaxf(b.y, 0.f)),
                           0.5f * (fmaxf(a.z, 0.f) + fmaxf(b.z, 0.f)),
                           0.5f * (fmaxf(a.w, 0.f) + fmaxf(b.w, 0.f)));
    ((float4*)dst)[i] = r;
}

// ---------------- launch ----------------
extern "C" void kernel_launch(void* const* d_in, const int* in_sizes, int n_in,
                              void* d_out, int out_size) {
    const float* x    = (const float*)d_in[0];
    const float* d2an = (const float*)d_in[1];
    const int*   ei0  = (const int*)  d_in[2];
    const float* ew0  = (const float*)d_in[3];
    const int*   ei1  = (const int*)  d_in[4];
    const float* ew1  = (const float*)d_in[5];
    const float* nW1  = (const float*)d_in[6];
    const float* nW2  = (const float*)d_in[7];
    const float* W1a  = (const float*)d_in[8];
    const float* W1b  = (const float*)d_in[9];
    const float* W2a  = (const float*)d_in[10];
    const float* W2b  = (const float*)d_in[11];
    const float* W3a  = (const float*)d_in[12];
    const float* W3b  = (const float*)d_in[13];
    const float* W4a  = (const float*)d_in[14];
    const float* W4b  = (const float*)d_in[15];
    float* out = (float*)d_out;

    const int TB = 256;
    k_deg_init <<<(NN + TB - 1) / TB, TB>>>();
    k_deg_count<<<(EE + TB - 1) / TB, TB>>>(ei0, ei1);
    k_dis      <<<(NN + TB - 1) / TB, TB>>>();

    k_build_xc <<<NN, 256>>>(x, d2an);
    k_build_Wc <<<(MH * KC + TB - 1) / TB, TB>>>(W1a, W1b, W2a, W2b, nW1, nW2);

    dim3 gg((NN + 127) / 128, MH / 128);
    const int sg = (EE * 32 + TB - 1) / TB;
    const int cg = (NN * 32 + TB - 1) / TB;

    // ---- stage 1 ----
    k_gemm    <<<gg, 256>>>(0);
    k_selfinit<<<cg, TB>>>();
    k_scatter <<<sg, TB>>>(ei0, ew0, 0);
    k_scatter <<<sg, TB>>>(ei1, ew1, 1);
    k_combine <<<cg, TB>>>(nullptr, 0);          // -> g_xm

    // ---- stage 2 ----
    k_build_Wc2<<<(MH * ENC + TB - 1) / TB, TB>>>(W3a, W3b, W4a, W4b);
    k_gemm    <<<gg, 256>>>(1);
    k_selfinit<<<cg, TB>>>();
    k_scatter <<<sg, TB>>>(ei0, ew0, 0);
    k_scatter <<<sg, TB>>>(ei1, ew1, 1);
    k_combine <<<cg, TB>>>(out, 1);              // -> d_out
}

// round 4
// speedup vs baseline: 1.5826x; 1.3150x over previous
#include <cuda_runtime.h>
#include <cuda_fp16.h>
#include <math.h>

#define NN   100000
#define EE   1600000
#define ENC  128
#define PI_  98
#define KIN  226          // ENC + PI
#define KC   232          // KIN padded to multiple of 8
#define MH   512          // 4 stacked [*,128] outputs
#define EMB  128
#define NB_SCAN 98        // ceil(NN/1024)

typedef unsigned long long ull;

// ---------------- scratch (static device globals; no allocation) ----------------
__device__ float   g_xc  [(size_t)NN * KC];     // concat(x, d2an) zero-padded
__device__ __half2 g_hh  [(size_t)NN * (MH/2)]; // stacked h1/h2 (fp16)
__device__ float   g_xm  [(size_t)NN * EMB];
__device__ float   g_Wc  [MH * KC];             // stage-1 fused weights
__device__ float   g_Wc2 [MH * ENC];            // stage-2 stacked weights

// CSR (per edge set)
__device__ int     g_cnt   [2][NN];
__device__ int     g_rowptr[2][NN + 1];
__device__ int     g_cur   [2][NN];
__device__ int     g_bsum  [NB_SCAN];
__device__ float   g_dis   [2][NN];
__device__ int     g_csrc  [2][EE];
__device__ float   g_cdn   [2][EE];
__device__ float   g_ceinv [2][EE];

// ---------------- f32x2 helpers ----------------
__device__ __forceinline__ void fma2(ull &d, ull a, ull b) {
    asm("fma.rn.f32x2 %0, %1, %2, %0;" : "+l"(d) : "l"(a), "l"(b));
}
__device__ __forceinline__ ull pack2(float v) {
    ull r; asm("mov.b64 %0, {%1, %1};" : "=l"(r) : "f"(v)); return r;
}
__device__ __forceinline__ float2 unpack2(ull v) {
    float2 r; asm("mov.b64 {%0, %1}, %2;" : "=f"(r.x), "=f"(r.y) : "l"(v)); return r;
}

// ---------------- CSR build ----------------
__global__ void k_zero_cnt() {
    int i = blockIdx.x * blockDim.x + threadIdx.x;
    if (i < NN) { g_cnt[0][i] = 0; g_cnt[1][i] = 0; }
}

__global__ void k_hist(const int* __restrict__ ei0, const int* __restrict__ ei1) {
    int e = blockIdx.x * blockDim.x + threadIdx.x;
    if (e < EE) {
        atomicAdd(&g_cnt[0][ei0[EE + e]], 1);
        atomicAdd(&g_cnt[1][ei1[EE + e]], 1);
    }
}

__global__ void k_dis_k() {
    int i = blockIdx.x * blockDim.x + threadIdx.x;
    if (i < NN) {
        g_dis[0][i] = rsqrtf((float)(g_cnt[0][i] + 1));   // +1 self loop
        g_dis[1][i] = rsqrtf((float)(g_cnt[1][i] + 1));
    }
}

__global__ void k_scan1(int which) {
    __shared__ int sh[1024];
    int tid = threadIdx.x;
    int i = blockIdx.x * 1024 + tid;
    int v = (i < NN) ? g_cnt[which][i] : 0;
    sh[tid] = v; __syncthreads();
#pragma unroll
    for (int off = 1; off < 1024; off <<= 1) {
        int t = (tid >= off) ? sh[tid - off] : 0;
        __syncthreads();
        sh[tid] += t;
        __syncthreads();
    }
    if (i < NN) g_rowptr[which][i] = sh[tid] - v;     // exclusive
    if (tid == 1023) g_bsum[blockIdx.x] = sh[1023];
}

__global__ void k_scan2() {
    if (threadIdx.x == 0) {
        int s = 0;
        for (int i = 0; i < NB_SCAN; i++) { int t = g_bsum[i]; g_bsum[i] = s; s += t; }
    }
}

__global__ void k_scan3(int which) {
    int i = blockIdx.x * blockDim.x + threadIdx.x;
    if (i < NN) {
        int v = g_rowptr[which][i] + g_bsum[i >> 10];
        g_rowptr[which][i] = v;
        g_cur[which][i] = v;
    }
    if (i == 0) g_rowptr[which][NN] = EE;
}

__global__ void k_fill(const int* __restrict__ ei, const float* __restrict__ ew, int which) {
    int e = blockIdx.x * blockDim.x + threadIdx.x;
    if (e >= EE) return;
    int r = ei[e];
    int c = ei[EE + e];
    float w = ew[e];
    int p = atomicAdd(&g_cur[which][c], 1);
    g_csrc[which][p]  = r;
    g_cdn[which][p]   = g_dis[which][r] * g_dis[which][c];
    g_ceinv[which][p] = (w > 0.0f) ? fminf(rsqrtf(w), 1.0f) : 0.0f;
}

// ---------------- build concat input (block per node, coalesced) ----------------
__global__ void k_build_xc(const float* __restrict__ x, const float* __restrict__ d2) {
    int n = blockIdx.x;
    int k = threadIdx.x;
    if (k >= KC) return;
    float v = 0.0f;
    if (k < ENC)       v = x[n * ENC + k];
    else if (k < KIN)  v = d2[n * PI_ + (k - ENC)];
    g_xc[(size_t)n * KC + k] = v;
}

// ---------------- fused weights: Wc[m] = Wsel[m%128] @ nodeWsel ----------------
__global__ void k_build_Wc(const float* __restrict__ W1a, const float* __restrict__ W1b,
                           const float* __restrict__ W2a, const float* __restrict__ W2b,
                           const float* __restrict__ nW1, const float* __restrict__ nW2) {
    int i = blockIdx.x * blockDim.x + threadIdx.x;
    if (i >= MH * KC) return;
    int m = i / KC, k = i - m * KC;
    float v = 0.0f;
    if (k < KIN) {
        const float* Ws = (m < 128) ? W1a : (m < 256) ? W1b : (m < 384) ? W2a : W2b;
        const float* nW = (m < 256) ? nW1 : nW2;
        int mm = m & 127;
        float s = 0.0f;
#pragma unroll 8
        for (int j = 0; j < ENC; j++) s = fmaf(Ws[mm * ENC + j], nW[j * KIN + k], s);
        v = s;
    }
    g_Wc[i] = v;
}

__global__ void k_build_Wc2(const float* __restrict__ W3a, const float* __restrict__ W3b,
                            const float* __restrict__ W4a, const float* __restrict__ W4b) {
    int i = blockIdx.x * blockDim.x + threadIdx.x;
    if (i >= MH * ENC) return;
    int m = i / ENC, k = i - m * ENC;
    const float* Ws = (m < 128) ? W3a : (m < 256) ? W3b : (m < 384) ? W4a : W4b;
    g_Wc2[i] = Ws[(m & 127) * ENC + k];
}

// ---------------- GEMM: C[N,512] = A[N,K] * W[512,K]^T, packed f32x2, fp16 out ----------------
__global__ __launch_bounds__(256, 2)
void k_gemm(int stage) {
    const float* __restrict__ A = stage ? g_xm  : g_xc;
    const float* __restrict__ W = stage ? g_Wc2 : g_Wc;
    const int K = stage ? ENC : KC;

    __shared__ float As[2][8][128];
    __shared__ float Bs[2][8][128];

    const int tid = threadIdx.x;
    const int bn  = blockIdx.x * 128;
    const int bm  = blockIdx.y * 128;
    const int lr  = tid >> 1;
    const int lk  = (tid & 1) * 4;
    const int tx  = tid & 15;
    const int ty  = tid >> 4;

    const int  arow = bn + lr;
    const bool aval = (arow < NN);
    const float* Abase = A + (size_t)arow * K + lk;
    const float* Wbase = W + (size_t)(bm + lr) * K + lk;

    ull acc[8][4];
#pragma unroll
    for (int i = 0; i < 8; i++)
#pragma unroll
        for (int j = 0; j < 4; j++) acc[i][j] = 0ULL;

    const int nk = K >> 3;

    auto load_tile = [&](int kt, int buf) {
        float4 a = make_float4(0.f, 0.f, 0.f, 0.f);
        if (aval) a = *(const float4*)(Abase + kt * 8);
        As[buf][lk + 0][lr] = a.x;
        As[buf][lk + 1][lr] = a.y;
        As[buf][lk + 2][lr] = a.z;
        As[buf][lk + 3][lr] = a.w;
        float4 w = *(const float4*)(Wbase + kt * 8);
        Bs[buf][lk + 0][lr] = w.x;
        Bs[buf][lk + 1][lr] = w.y;
        Bs[buf][lk + 2][lr] = w.z;
        Bs[buf][lk + 3][lr] = w.w;
    };

    load_tile(0, 0);
    __syncthreads();

    for (int kt = 0; kt < nk; kt++) {
        int buf = kt & 1;
        if (kt + 1 < nk) load_tile(kt + 1, buf ^ 1);
#pragma unroll
        for (int k = 0; k < 8; k++) {
            float4 a0 = *(const float4*)&As[buf][k][ty * 4];
            float4 a1 = *(const float4*)&As[buf][k][64 + ty * 4];
            ulonglong2 b01 = *(const ulonglong2*)&Bs[buf][k][tx * 4];
            ulonglong2 b23 = *(const ulonglong2*)&Bs[buf][k][64 + tx * 4];
            float av[8] = {a0.x, a0.y, a0.z, a0.w, a1.x, a1.y, a1.z, a1.w};
#pragma unroll
            for (int i = 0; i < 8; i++) {
                ull ap = pack2(av[i]);
                fma2(acc[i][0], ap, b01.x);
                fma2(acc[i][1], ap, b01.y);
                fma2(acc[i][2], ap, b23.x);
                fma2(acc[i][3], ap, b23.y);
            }
        }
        __syncthreads();
    }

#pragma unroll
    for (int h = 0; h < 2; h++) {
#pragma unroll
        for (int ii = 0; ii < 4; ii++) {
            int row = bn + h * 64 + ty * 4 + ii;
            if (row < NN) {
                __half2* Cr = g_hh + (size_t)row * (MH / 2) + (bm >> 1);
#pragma unroll
                for (int g = 0; g < 2; g++) {
                    float2 p0 = unpack2(acc[h * 4 + ii][g * 2 + 0]);
                    float2 p1 = unpack2(acc[h * 4 + ii][g * 2 + 1]);
                    __half2 q0 = __floats2half2_rn(p0.x, p0.y);
                    __half2 q1 = __floats2half2_rn(p1.x, p1.y);
                    uint2 st;
                    st.x = *(unsigned*)&q0;
                    st.y = *(unsigned*)&q1;
                    *(uint2*)(Cr + (g * 64 + tx * 4) / 2) = st;
                }
            }
        }
    }
}

// ---------------- fused aggregation: warp per node, both edge sets, relu+mix ----------------
__global__ __launch_bounds__(256)
void k_agg(float* __restrict__ dst_ext, int use_ext) {
    int n = blockIdx.x * 8 + (threadIdx.x >> 5);
    if (n >= NN) return;
    int lane = threadIdx.x & 31;
    float* dst = use_ext ? dst_ext : g_xm;   // g_xm resolved DEVICE-side

    const __half2* hr = g_hh + (size_t)n * (MH / 2) + lane * 2;

    // self-loop init: acc = dis^2 * h1 + h2  (einv(1)=1)
    float s0 = g_dis[0][n]; s0 *= s0;
    float s1 = g_dis[1][n]; s1 *= s1;

    float2 a0 = __half22float2(hr[0]),   a1 = __half22float2(hr[1]);
    float2 b0 = __half22float2(hr[64]),  b1 = __half22float2(hr[65]);
    float2 c0 = __half22float2(hr[128]), c1 = __half22float2(hr[129]);
    float2 d0 = __half22float2(hr[192]), d1 = __half22float2(hr[193]);

    float acc0[4] = { fmaf(s0, a0.x, b0.x), fmaf(s0, a0.y, b0.y),
                      fmaf(s0, a1.x, b1.x), fmaf(s0, a1.y, b1.y) };
    float acc1[4] = { fmaf(s1, c0.x, d0.x), fmaf(s1, c0.y, d0.y),
                      fmaf(s1, c1.x, d1.x), fmaf(s1, c1.y, d1.y) };

    // edge set 0 -> acc0 (h cols [0,256))
    {
        int beg = g_rowptr[0][n], end = g_rowptr[0][n + 1];
        for (int j = beg; j < end; j++) {
            int   r    = g_csrc[0][j];
            float dn   = g_cdn[0][j];
            float einv = g_ceinv[0][j];
            const __half2* hp = g_hh + (size_t)r * (MH / 2) + lane * 2;
            float2 fa0 = __half22float2(hp[0]);
            float2 fa1 = __half22float2(hp[1]);
            float2 fb0 = __half22float2(hp[64]);
            float2 fb1 = __half22float2(hp[65]);
            acc0[0] = fmaf(dn, fa0.x, fmaf(einv, fb0.x, acc0[0]));
            acc0[1] = fmaf(dn, fa0.y, fmaf(einv, fb0.y, acc0[1]));
            acc0[2] = fmaf(dn, fa1.x, fmaf(einv, fb1.x, acc0[2]));
            acc0[3] = fmaf(dn, fa1.y, fmaf(einv, fb1.y, acc0[3]));
        }
    }
    // edge set 1 -> acc1 (h cols [256,512))
    {
        int beg = g_rowptr[1][n], end = g_rowptr[1][n + 1];
        for (int j = beg; j < end; j++) {
            int   r    = g_csrc[1][j];
            float dn   = g_cdn[1][j];
            float einv = g_ceinv[1][j];
            const __half2* hp = g_hh + (size_t)r * (MH / 2) + 128 + lane * 2;
            float2 fa0 = __half22float2(hp[0]);
            float2 fa1 = __half22float2(hp[1]);
            float2 fb0 = __half22float2(hp[64]);
            float2 fb1 = __half22float2(hp[65]);
            acc1[0] = fmaf(dn, fa0.x, fmaf(einv, fb0.x, acc1[0]));
            acc1[1] = fmaf(dn, fa0.y, fmaf(einv, fb0.y, acc1[1]));
            acc1[2] = fmaf(dn, fa1.x, fmaf(einv, fb1.x, acc1[2]));
            acc1[3] = fmaf(dn, fa1.y, fmaf(einv, fb1.y, acc1[3]));
        }
    }

    float4 o = make_float4(
        0.5f * (fmaxf(acc0[0], 0.f) + fmaxf(acc1[0], 0.f)),
        0.5f * (fmaxf(acc0[1], 0.f) + fmaxf(acc1[1], 0.f)),
        0.5f * (fmaxf(acc0[2], 0.f) + fmaxf(acc1[2], 0.f)),
        0.5f * (fmaxf(acc0[3], 0.f) + fmaxf(acc1[3], 0.f)));
    *(float4*)(dst + (size_t)n * EMB + lane * 4) = o;
}

// ---------------- launch ----------------
extern "C" void kernel_launch(void* const* d_in, const int* in_sizes, int n_in,
                              void* d_out, int out_size) {
    const float* x    = (const float*)d_in[0];
    const float* d2an = (const float*)d_in[1];
    const int*   ei0  = (const int*)  d_in[2];
    const float* ew0  = (const float*)d_in[3];
    const int*   ei1  = (const int*)  d_in[4];
    const float* ew1  = (const float*)d_in[5];
    const float* nW1  = (const float*)d_in[6];
    const float* nW2  = (const float*)d_in[7];
    const float* W1a  = (const float*)d_in[8];
    const float* W1b  = (const float*)d_in[9];
    const float* W2a  = (const float*)d_in[10];
    const float* W2b  = (const float*)d_in[11];
    const float* W3a  = (const float*)d_in[12];
    const float* W3b  = (const float*)d_in[13];
    const float* W4a  = (const float*)d_in[14];
    const float* W4b  = (const float*)d_in[15];
    float* out = (float*)d_out;

    const int TB = 256;
    const int ng = (NN + TB - 1) / TB;
    const int eg = (EE + TB - 1) / TB;

    // ---- CSR build (both edge sets) ----
    k_zero_cnt<<<ng, TB>>>();
    k_hist    <<<eg, TB>>>(ei0, ei1);
    k_dis_k   <<<ng, TB>>>();
    k_scan1<<<NB_SCAN, 1024>>>(0);
    k_scan2<<<1, 32>>>();
    k_scan3<<<ng, TB>>>(0);
    k_scan1<<<NB_SCAN, 1024>>>(1);
    k_scan2<<<1, 32>>>();
    k_scan3<<<ng, TB>>>(1);
    k_fill<<<eg, TB>>>(ei0, ew0, 0);
    k_fill<<<eg, TB>>>(ei1, ew1, 1);

    // ---- weights / inputs ----
    k_build_xc <<<NN, 256>>>(x, d2an);
    k_build_Wc <<<(MH * KC + TB - 1) / TB, TB>>>(W1a, W1b, W2a, W2b, nW1, nW2);
    k_build_Wc2<<<(MH * ENC + TB - 1) / TB, TB>>>(W3a, W3b, W4a, W4b);

    dim3 gg((NN + 127) / 128, MH / 128);
    const int ag = (NN + 7) / 8;

    // ---- stage 1 ----
    k_gemm<<<gg, 256>>>(0);
    k_agg <<<ag, 256>>>(nullptr, 0);   // -> g_xm (device-side)

    // ---- stage 2 ----
    k_gemm<<<gg, 256>>>(1);
    k_agg <<<ag, 256>>>(out, 1);       // -> d_out
}

// round 6
// speedup vs baseline: 2.7892x; 1.7625x over previous
#include <cuda_runtime.h>
#include <cuda_fp16.h>
#include <cstdint>
#include <cstdio>
#include <math.h>

#define NN   100000
#define EE   1600000
#define ENC  128
#define PI_  98
#define KIN  226          // ENC + PI
#define KCH  240          // KIN padded to multiple of 16
#define MH   512          // 4 stacked [*,128] outputs
#define EMB  128
#define NB_SCAN 98        // ceil(NN/1024)

// ---------------- scratch (static device globals; no allocation) ----------------
__device__ __half   g_xh [(size_t)NN * KCH];     // concat(x,d2an) fp16, zero-padded
__device__ __half   g_wh1[MH * KCH];             // stage-1 fused weights fp16
__device__ __half   g_wh2[MH * ENC];             // stage-2 stacked weights fp16
__device__ __half   g_xmh[(size_t)NN * ENC];     // stage-1 result (fp16, input to stage-2 GEMM)
__device__ __half2  g_hh [(size_t)NN * (MH/2)];  // GEMM output h (fp16)

// CSR (per edge set)
__device__ int     g_cnt   [2][NN];
__device__ int     g_rowptr[2][NN + 1];
__device__ int     g_cur   [2][NN];
__device__ int     g_bsum  [NB_SCAN];
__device__ float   g_dis   [2][NN];
__device__ int     g_csrc  [2][EE];
__device__ float   g_cdn   [2][EE];
__device__ float   g_ceinv [2][EE];

// ---------------- mma helpers (builtin types only) ----------------
__device__ __forceinline__ void ldsm4(unsigned &r0, unsigned &r1, unsigned &r2, unsigned &r3,
                                      unsigned addr) {
    asm volatile("ldmatrix.sync.aligned.m8n8.x4.shared.b16 {%0,%1,%2,%3}, [%4];"
                 : "=r"(r0), "=r"(r1), "=r"(r2), "=r"(r3) : "r"(addr));
}
__device__ __forceinline__ void ldsm2(unsigned &r0, unsigned &r1, unsigned addr) {
    asm volatile("ldmatrix.sync.aligned.m8n8.x2.shared.b16 {%0,%1}, [%2];"
                 : "=r"(r0), "=r"(r1) : "r"(addr));
}
__device__ __forceinline__ void mma16816(float &c0, float &c1, float &c2, float &c3,
                                         unsigned a0, unsigned a1, unsigned a2, unsigned a3,
                                         unsigned b0, unsigned b1) {
    asm volatile("mma.sync.aligned.m16n8k16.row.col.f32.f16.f16.f32 "
                 "{%0,%1,%2,%3}, {%4,%5,%6,%7}, {%8,%9}, {%0,%1,%2,%3};"
                 : "+f"(c0), "+f"(c1), "+f"(c2), "+f"(c3)
                 : "r"(a0), "r"(a1), "r"(a2), "r"(a3), "r"(b0), "r"(b1));
}

// ---------------- CSR build ----------------
__global__ void k_zero_cnt() {
    int i = blockIdx.x * blockDim.x + threadIdx.x;
    if (i < NN) { g_cnt[0][i] = 0; g_cnt[1][i] = 0; }
}

__global__ void k_hist(const int* __restrict__ ei0, const int* __restrict__ ei1) {
    int e = blockIdx.x * blockDim.x + threadIdx.x;
    if (e < EE) {
        atomicAdd(&g_cnt[0][ei0[EE + e]], 1);
        atomicAdd(&g_cnt[1][ei1[EE + e]], 1);
    }
}

__global__ void k_dis_k() {
    int i = blockIdx.x * blockDim.x + threadIdx.x;
    if (i < NN) {
        g_dis[0][i] = rsqrtf((float)(g_cnt[0][i] + 1));   // +1 self loop
        g_dis[1][i] = rsqrtf((float)(g_cnt[1][i] + 1));
    }
}

__global__ void k_scan1(int which) {
    __shared__ int sh[1024];
    int tid = threadIdx.x;
    int i = blockIdx.x * 1024 + tid;
    int v = (i < NN) ? g_cnt[which][i] : 0;
    sh[tid] = v; __syncthreads();
#pragma unroll
    for (int off = 1; off < 1024; off <<= 1) {
        int t = (tid >= off) ? sh[tid - off] : 0;
        __syncthreads();
        sh[tid] += t;
        __syncthreads();
    }
    if (i < NN) g_rowptr[which][i] = sh[tid] - v;     // exclusive
    if (tid == 1023) g_bsum[blockIdx.x] = sh[1023];
}

__global__ void k_scan2() {
    if (threadIdx.x == 0) {
        int s = 0;
        for (int i = 0; i < NB_SCAN; i++) { int t = g_bsum[i]; g_bsum[i] = s; s += t; }
    }
}

__global__ void k_scan3(int which) {
    int i = blockIdx.x * blockDim.x + threadIdx.x;
    if (i < NN) {
        int v = g_rowptr[which][i] + g_bsum[i >> 10];
        g_rowptr[which][i] = v;
        g_cur[which][i] = v;
    }
    if (i == 0) g_rowptr[which][NN] = EE;
}

__global__ void k_fill(const int* __restrict__ ei, const float* __restrict__ ew, int which) {
    int e = blockIdx.x * blockDim.x + threadIdx.x;
    if (e >= EE) return;
    int r = ei[e];
    int c = ei[EE + e];
    float w = ew[e];
    int p = atomicAdd(&g_cur[which][c], 1);
    g_csrc[which][p]  = r;
    g_cdn[which][p]   = g_dis[which][r] * g_dis[which][c];
    g_ceinv[which][p] = (w > 0.0f) ? fminf(rsqrtf(w), 1.0f) : 0.0f;
}

// ---------------- build concat input (block per node, coalesced, fp16) ----------------
__global__ void k_build_xc(const float* __restrict__ x, const float* __restrict__ d2) {
    int n = blockIdx.x;
    int k = threadIdx.x;
    if (k >= KCH) return;
    float v = 0.0f;
    if (k < ENC)       v = x[n * ENC + k];
    else if (k < KIN)  v = d2[n * PI_ + (k - ENC)];
    g_xh[(size_t)n * KCH + k] = __float2half(v);
}

// ---------------- fused weights: Wc[m] = Wsel[m%128] @ nodeWsel (fp16 out) ----------------
__global__ void k_build_Wc(const float* __restrict__ W1a, const float* __restrict__ W1b,
                           const float* __restrict__ W2a, const float* __restrict__ W2b,
                           const float* __restrict__ nW1, const float* __restrict__ nW2) {
    int i = blockIdx.x * blockDim.x + threadIdx.x;
    if (i >= MH * KCH) return;
    int m = i / KCH, k = i - m * KCH;
    float v = 0.0f;
    if (k < KIN) {
        const float* Ws = (m < 128) ? W1a : (m < 256) ? W1b : (m < 384) ? W2a : W2b;
        const float* nW = (m < 256) ? nW1 : nW2;
        int mm = m & 127;
        float s = 0.0f;
#pragma unroll 8
        for (int j = 0; j < ENC; j++) s = fmaf(Ws[mm * ENC + j], nW[j * KIN + k], s);
        v = s;
    }
    g_wh1[i] = __float2half(v);
}

__global__ void k_build_Wc2(const float* __restrict__ W3a, const float* __restrict__ W3b,
                            const float* __restrict__ W4a, const float* __restrict__ W4b) {
    int i = blockIdx.x * blockDim.x + threadIdx.x;
    if (i >= MH * ENC) return;
    int m = i / ENC, k = i - m * ENC;
    const float* Ws = (m < 128) ? W3a : (m < 256) ? W3b : (m < 384) ? W4a : W4b;
    g_wh2[i] = __float2half(Ws[(m & 127) * ENC + k]);
}

// ---------------- tensor-core GEMM: C[N,512] = A[N,K] * W[512,K]^T ----------------
// 128x128 CTA tile, 8 warps (2x4), warp tile 64x32, k-chunk 16, double buffered.
// smem rows padded to 24 halves (48B).
__global__ __launch_bounds__(256, 2)
void k_gemm_mma(int stage) {
    const __half* __restrict__ A = stage ? g_xmh : g_xh;
    const __half* __restrict__ B = stage ? g_wh2 : g_wh1;
    const int K  = stage ? ENC : KCH;
    const int nk = K >> 4;

    __shared__ __align__(16) __half As[2][128 * 24];
    __shared__ __align__(16) __half Bs[2][128 * 24];

    const int tid  = threadIdx.x;
    const int lane = tid & 31;
    const int warp = tid >> 5;
    const int wm   = warp >> 2;        // 0..1
    const int wn   = warp & 3;         // 0..3
    const int bn   = blockIdx.x * 128; // node base
    const int bm   = blockIdx.y * 128; // out-col base

    // gmem->smem load mapping (one uint4 = 8 halves per thread per tile)
    const int  lrow = tid >> 1;
    const int  lcol = (tid & 1) * 8;
    const bool aval = (bn + lrow) < NN;
    const __half* Ab = A + (size_t)(aval ? (bn + lrow) : 0) * K + lcol;
    const __half* Bb = B + (size_t)(bm + lrow) * K + lcol;
    const int soff = lrow * 24 + lcol;           // halves

    // ldmatrix per-thread smem offsets (bytes)
    const unsigned as_base = (unsigned)__cvta_generic_to_shared(&As[0][0]);
    const unsigned bs_base = (unsigned)__cvta_generic_to_shared(&Bs[0][0]);
    const unsigned a_off = ((wm * 64 + (lane & 15)) * 24 + (lane >> 4) * 8) * 2;
    const unsigned b_off = ((wn * 32 + (lane & 7)) * 24 + ((lane >> 3) & 1) * 8) * 2;
    const unsigned BUFB = 128 * 24 * 2;          // bytes per buffer

    float c[4][4][4];
#pragma unroll
    for (int mi = 0; mi < 4; mi++)
#pragma unroll
        for (int ni = 0; ni < 4; ni++)
#pragma unroll
            for (int q = 0; q < 4; q++) c[mi][ni][q] = 0.0f;

    // prefetch tile 0
    {
        uint4 av = make_uint4(0, 0, 0, 0);
        if (aval) av = *(const uint4*)Ab;
        uint4 bv = *(const uint4*)Bb;
        *(uint4*)&As[0][soff] = av;
        *(uint4*)&Bs[0][soff] = bv;
    }
    __syncthreads();

    for (int ks = 0; ks < nk; ks++) {
        const int buf = ks & 1;
        uint4 av = make_uint4(0, 0, 0, 0);
        uint4 bv = make_uint4(0, 0, 0, 0);
        const bool more = (ks + 1 < nk);
        if (more) {
            if (aval) av = *(const uint4*)(Ab + (ks + 1) * 16);
            bv = *(const uint4*)(Bb + (ks + 1) * 16);
        }

        // fragments
        unsigned a[4][4], b[4][2];
#pragma unroll
        for (int mi = 0; mi < 4; mi++)
            ldsm4(a[mi][0], a[mi][1], a[mi][2], a[mi][3],
                  as_base + buf * BUFB + a_off + mi * 16 * 48);
#pragma unroll
        for (int ni = 0; ni < 4; ni++)
            ldsm2(b[ni][0], b[ni][1],
                  bs_base + buf * BUFB + b_off + ni * 8 * 48);

#pragma unroll
        for (int mi = 0; mi < 4; mi++)
#pragma unroll
            for (int ni = 0; ni < 4; ni++)
                mma16816(c[mi][ni][0], c[mi][ni][1], c[mi][ni][2], c[mi][ni][3],
                         a[mi][0], a[mi][1], a[mi][2], a[mi][3],
                         b[ni][0], b[ni][1]);

        if (more) {
            *(uint4*)&As[buf ^ 1][soff] = av;
            *(uint4*)&Bs[buf ^ 1][soff] = bv;
        }
        __syncthreads();
    }

    // store C as fp16 half2
#pragma unroll
    for (int mi = 0; mi < 4; mi++) {
        int row = bn + wm * 64 + mi * 16 + (lane >> 2);
#pragma unroll
        for (int ni = 0; ni < 4; ni++) {
            int colh2 = ((bm + wn * 32 + ni * 8) >> 1) + (lane & 3);
            if (row < NN)
                g_hh[(size_t)row * (MH / 2) + colh2] =
                    __floats2half2_rn(c[mi][ni][0], c[mi][ni][1]);
            if (row + 8 < NN)
                g_hh[(size_t)(row + 8) * (MH / 2) + colh2] =
                    __floats2half2_rn(c[mi][ni][2], c[mi][ni][3]);
        }
    }
}

// ---------------- fused aggregation: warp per node, both edge sets, relu+mix ----------------
__global__ __launch_bounds__(256)
void k_agg(float* __restrict__ dst_ext, int use_ext) {
    int n = blockIdx.x * 8 + (threadIdx.x >> 5);
    if (n >= NN) return;
    int lane = threadIdx.x & 31;

    const __half2* hr = g_hh + (size_t)n * (MH / 2) + lane * 2;

    // self-loop init: acc = dis^2 * h1 + h2  (einv(1)=1)
    float s0 = g_dis[0][n]; s0 *= s0;
    float s1 = g_dis[1][n]; s1 *= s1;

    float2 a0 = __half22float2(hr[0]),   a1 = __half22float2(hr[1]);
    float2 b0 = __half22float2(hr[64]),  b1 = __half22float2(hr[65]);
    float2 c0 = __half22float2(hr[128]), c1 = __half22float2(hr[129]);
    float2 d0 = __half22float2(hr[192]), d1 = __half22float2(hr[193]);

    float acc0[4] = { fmaf(s0, a0.x, b0.x), fmaf(s0, a0.y, b0.y),
                      fmaf(s0, a1.x, b1.x), fmaf(s0, a1.y, b1.y) };
    float acc1[4] = { fmaf(s1, c0.x, d0.x), fmaf(s1, c0.y, d0.y),
                      fmaf(s1, c1.x, d1.x), fmaf(s1, c1.y, d1.y) };

    // edge set 0 -> acc0 (h cols [0,256))
    {
        int beg = g_rowptr[0][n], end = g_rowptr[0][n + 1];
        for (int j = beg; j < end; j++) {
            int   r    = g_csrc[0][j];
            float dn   = g_cdn[0][j];
            float einv = g_ceinv[0][j];
            const __half2* hp = g_hh + (size_t)r * (MH / 2) + lane * 2;
            float2 fa0 = __half22float2(hp[0]);
            float2 fa1 = __half22float2(hp[1]);
            float2 fb0 = __half22float2(hp[64]);
            float2 fb1 = __half22float2(hp[65]);
            acc0[0] = fmaf(dn, fa0.x, fmaf(einv, fb0.x, acc0[0]));
            acc0[1] = fmaf(dn, fa0.y, fmaf(einv, fb0.y, acc0[1]));
            acc0[2] = fmaf(dn, fa1.x, fmaf(einv, fb1.x, acc0[2]));
            acc0[3] = fmaf(dn, fa1.y, fmaf(einv, fb1.y, acc0[3]));
        }
    }
    // edge set 1 -> acc1 (h cols [256,512))
    {
        int beg = g_rowptr[1][n], end = g_rowptr[1][n + 1];
        for (int j = beg; j < end; j++) {
            int   r    = g_csrc[1][j];
            float dn   = g_cdn[1][j];
            float einv = g_ceinv[1][j];
            const __half2* hp = g_hh + (size_t)r * (MH / 2) + 128 + lane * 2;
            float2 fa0 = __half22float2(hp[0]);
            float2 fa1 = __half22float2(hp[1]);
            float2 fb0 = __half22float2(hp[64]);
            float2 fb1 = __half22float2(hp[65]);
            acc1[0] = fmaf(dn, fa0.x, fmaf(einv, fb0.x, acc1[0]));
            acc1[1] = fmaf(dn, fa0.y, fmaf(einv, fb0.y, acc1[1]));
            acc1[2] = fmaf(dn, fa1.x, fmaf(einv, fb1.x, acc1[2]));
            acc1[3] = fmaf(dn, fa1.y, fmaf(einv, fb1.y, acc1[3]));
        }
    }

    float4 o = make_float4(
        0.5f * (fmaxf(acc0[0], 0.f) + fmaxf(acc1[0], 0.f)),
        0.5f * (fmaxf(acc0[1], 0.f) + fmaxf(acc1[1], 0.f)),
        0.5f * (fmaxf(acc0[2], 0.f) + fmaxf(acc1[2], 0.f)),
        0.5f * (fmaxf(acc0[3], 0.f) + fmaxf(acc1[3], 0.f)));

    if (use_ext) {
        *(float4*)(dst_ext + (size_t)n * EMB + lane * 4) = o;
    } else {
        __half2 h0 = __floats2half2_rn(o.x, o.y);
        __half2 h1 = __floats2half2_rn(o.z, o.w);
        uint2 st;
        st.x = *(unsigned*)&h0;
        st.y = *(unsigned*)&h1;
        *(uint2*)(g_xmh + (size_t)n * ENC + lane * 4) = st;
    }
}

// ---------------- launch ----------------
extern "C" void kernel_launch(void* const* d_in, const int* in_sizes, int n_in,
                              void* d_out, int out_size) {
    const float* x    = (const float*)d_in[0];
    const float* d2an = (const float*)d_in[1];
    const int*   ei0  = (const int*)  d_in[2];
    const float* ew0  = (const float*)d_in[3];
    const int*   ei1  = (const int*)  d_in[4];
    const float* ew1  = (const float*)d_in[5];
    const float* nW1  = (const float*)d_in[6];
    const float* nW2  = (const float*)d_in[7];
    const float* W1a  = (const float*)d_in[8];
    const float* W1b  = (const float*)d_in[9];
    const float* W2a  = (const float*)d_in[10];
    const float* W2b  = (const float*)d_in[11];
    const float* W3a  = (const float*)d_in[12];
    const float* W3b  = (const float*)d_in[13];
    const float* W4a  = (const float*)d_in[14];
    const float* W4b  = (const float*)d_in[15];
    float* out = (float*)d_out;

    const int TB = 256;
    const int ng = (NN + TB - 1) / TB;
    const int eg = (EE + TB - 1) / TB;

    // ---- CSR build (both edge sets) ----
    k_zero_cnt<<<ng, TB>>>();
    k_hist    <<<eg, TB>>>(ei0, ei1);
    k_dis_k   <<<ng, TB>>>();
    k_scan1<<<NB_SCAN, 1024>>>(0);
    k_scan2<<<1, 32>>>();
    k_scan3<<<ng, TB>>>(0);
    k_scan1<<<NB_SCAN, 1024>>>(1);
    k_scan2<<<1, 32>>>();
    k_scan3<<<ng, TB>>>(1);
    k_fill<<<eg, TB>>>(ei0, ew0, 0);
    k_fill<<<eg, TB>>>(ei1, ew1, 1);

    // ---- weights / inputs ----
    k_build_xc <<<NN, 256>>>(x, d2an);
    k_build_Wc <<<(MH * KCH + TB - 1) / TB, TB>>>(W1a, W1b, W2a, W2b, nW1, nW2);
    k_build_Wc2<<<(MH * ENC + TB - 1) / TB, TB>>>(W3a, W3b, W4a, W4b);

    dim3 gg((NN + 127) / 128, MH / 128);
    const int ag = (NN + 7) / 8;

    // ---- stage 1 ----
    k_gemm_mma<<<gg, 256>>>(0);
    k_agg     <<<ag, 256>>>(nullptr, 0);   // -> g_xmh (device-side, fp16)

    // ---- stage 2 ----
    k_gemm_mma<<<gg, 256>>>(1);
    k_agg     <<<ag, 256>>>(out, 1);       // -> d_out (fp32)
}